// round 4
// baseline (speedup 1.0000x reference)
#include <cuda_runtime.h>
#include <math.h>

// UserCollaborativeFiltering:
//   T=64, U=142, I=4500, B=16384, K=10 (derived from in_sizes at launch).
// Inputs (metadata order):
//   d_in[0] qos_tensor  float32 [T,U,I]
//   d_in[1] user_avg    float32 [T,U]
//   d_in[2] user_sim_agg float32 [U,U]
//   d_in[3] user_id     int32   [B]
//   d_in[4] item_id     int32   [B]
//   d_in[5] time_id     int32   [B]
//   d_in[6] top_k       (scalar, fixed 10 — unused)
// Output: float32 [B]
//
// One warp per batch element. Each lane owns up to 5 users (ceil(142/32)).
// Iterative top-10 extraction via warp butterfly argmax (value, lowest-index
// tie-break to match jax.lax.top_k ordering). The rated-value r_vs and avg_v
// for winners come from the registers that already hold the gathered column.

#define JMAX 5  // ceil(142/32); assert at launch that U <= 32*JMAX

__global__ void __launch_bounds__(256) ucf_kernel(
    const float* __restrict__ qos,      // [T,U,I]
    const float* __restrict__ user_avg, // [T,U]
    const float* __restrict__ sim,      // [U,U]
    const int*   __restrict__ user_id,
    const int*   __restrict__ item_id,
    const int*   __restrict__ time_id,
    float*       __restrict__ out,
    int B, int U, int I)
{
    const int warp = blockIdx.x * (blockDim.x >> 5) + (threadIdx.x >> 5);
    if (warp >= B) return;
    const int lane = threadIdx.x & 31;

    const int u = user_id[warp];
    const int it = item_id[warp];
    const int t = time_id[warp];

    const float avg_u = user_avg[(size_t)t * U + u];
    const float* __restrict__ simrow = sim + (size_t)u * U;
    const float* __restrict__ avgrow = user_avg + (size_t)t * U;
    const float* __restrict__ qcol   = qos + ((size_t)t * U) * I + it;

    float mval[JMAX];  // masked similarity (top-k key); -INF for v >= U
    float qv[JMAX];    // qos[t, v, item] (= r_vs if selected)
    float av[JMAX];    // user_avg[t, v]

    #pragma unroll
    for (int j = 0; j < JMAX; j++) {
        const int v = j * 32 + lane;
        const bool ok = v < U;
        // Scattered gather: stride I floats between lanes' users -> one
        // 32B sector per load. This is the kernel's entire DRAM cost.
        float q = ok ? __ldg(qcol + (size_t)v * I) : 0.0f;
        float s = ok ? __ldg(simrow + v) : 0.0f;
        float a = ok ? __ldg(avgrow + v) : 0.0f;
        qv[j] = q;
        av[j] = a;
        // Reference: sim_m = where(item_rated, sim_u, 0.0). Zeros stay in
        // the top-k candidate pool (they can outrank negatives) but carry
        // zero weight. Only nonexistent users are excluded via -INF.
        mval[j] = ok ? ((q > 0.0f) ? s : 0.0f) : -INFINITY;
    }

    float contrib = 0.0f;  // sum_k top_sim_k * (r_vs_k - avg_v_k), unnormalized
    float simsum = 0.0f;   // sum_k top_sim_k

    #pragma unroll
    for (int k = 0; k < 10; k++) {
        // Lane-local argmax over the (up to) 5 owned users.
        float best = -INFINITY;
        int bj = 0;
        #pragma unroll
        for (int j = 0; j < JMAX; j++) {
            if (mval[j] > best) { best = mval[j]; bj = j; }
        }
        // code orders identically to global user index v = j*32 + lane,
        // so "smaller code wins ties" == jax top_k's lowest-index-first.
        int bc = (bj << 5) | lane;
        float bv = best;
        #pragma unroll
        for (int off = 16; off; off >>= 1) {
            float ov = __shfl_xor_sync(0xffffffffu, bv, off);
            int   oc = __shfl_xor_sync(0xffffffffu, bc, off);
            if (ov > bv || (ov == bv && oc < bc)) { bv = ov; bc = oc; }
        }
        // All lanes now agree on (bv, bc).
        const int wj = bc >> 5;
        const int wl = bc & 31;
        float d = 0.0f;
        if (lane == wl) {
            #pragma unroll
            for (int j = 0; j < JMAX; j++) {
                if (j == wj) { d = qv[j] - av[j]; mval[j] = -INFINITY; }
            }
        }
        d = __shfl_sync(0xffffffffu, d, wl);  // broadcast r_vs - avg_v
        contrib += bv * d;
        simsum  += bv;
    }

    if (lane == 0) {
        // Reference: w = top_sim / (sum + 1e-8); nan_to_num; pred = avg_u + sum(w * d).
        // Same denominator for all k -> pred = avg_u + contrib / s.
        const float s = simsum + 1e-8f;
        float p = contrib / s;
        if (!isfinite(p)) p = 0.0f;  // mirrors nan_to_num on degenerate sums
        out[warp] = avg_u + p;
    }
}

extern "C" void kernel_launch(void* const* d_in, const int* in_sizes, int n_in,
                              void* d_out, int out_size)
{
    const float* qos      = (const float*)d_in[0];
    const float* user_avg = (const float*)d_in[1];
    const float* sim      = (const float*)d_in[2];
    const int*   user_id  = (const int*)d_in[3];
    const int*   item_id  = (const int*)d_in[4];
    const int*   time_id  = (const int*)d_in[5];
    float* out = (float*)d_out;

    // Derive shapes from element counts (robust to shape variants):
    // in_sizes[2] = U*U, in_sizes[1] = T*U, in_sizes[0] = T*U*I.
    int U = (int)(sqrt((double)in_sizes[2]) + 0.5);
    int T = in_sizes[1] / U;
    int I = in_sizes[0] / (T * U);
    int B = in_sizes[3];

    const int threads = 256;            // 8 warps per block
    const int wpb = threads / 32;
    const int blocks = (B + wpb - 1) / wpb;
    ucf_kernel<<<blocks, threads>>>(qos, user_avg, sim,
                                    user_id, item_id, time_id,
                                    out, B, U, I);
}

// round 5
// speedup vs baseline: 1.5323x; 1.5323x over previous
#include <cuda_runtime.h>
#include <math.h>

// UserCollaborativeFiltering — round 4.
// One warp per batch element; each lane owns up to 5 users (ceil(142/32)).
// Top-10 extraction via redux.sync (single-instruction warp max/min) instead
// of shfl butterflies: ~2.2x fewer warp instructions, ~2.5x shorter dependent
// chain per extraction. Winner contribution accumulated lane-locally and
// reduced once at the end.

#define JMAX 5  // ceil(142/32)

// Monotone float -> u32 map (order-preserving for all finite floats and ±inf).
__device__ __forceinline__ unsigned f2ord(float f) {
    unsigned b = __float_as_uint(f);
    return (b & 0x80000000u) ? ~b : (b | 0x80000000u);
}
__device__ __forceinline__ float ord2f(unsigned o) {
    unsigned b = (o & 0x80000000u) ? (o ^ 0x80000000u) : ~o;
    return __uint_as_float(b);
}

__global__ void __launch_bounds__(256) ucf_kernel(
    const float* __restrict__ qos,      // [T,U,I]
    const float* __restrict__ user_avg, // [T,U]
    const float* __restrict__ sim,      // [U,U]
    const int*   __restrict__ user_id,
    const int*   __restrict__ item_id,
    const int*   __restrict__ time_id,
    float*       __restrict__ out,
    int B, int U, int I)
{
    const int warp = blockIdx.x * (blockDim.x >> 5) + (threadIdx.x >> 5);
    if (warp >= B) return;
    const int lane = threadIdx.x & 31;

    const int u  = user_id[warp];
    const int it = item_id[warp];
    const int t  = time_id[warp];

    const float avg_u = user_avg[(size_t)t * U + u];
    const float* __restrict__ simrow = sim + (size_t)u * U;
    const float* __restrict__ avgrow = user_avg + (size_t)t * U;
    const float* __restrict__ qcol   = qos + ((size_t)t * U) * I + it;

    // o[j]: ordered key of masked similarity. 0 == "removed / nonexistent"
    // (0 maps to -NaN which never occurs as real data; every real sim,
    // including the masked 0.0 entries, orders strictly above it).
    unsigned o[JMAX];
    float    dv[JMAX];  // r_vs - avg_v, per owned user
    float    sv[JMAX];  // raw sim value (weight if selected)

    // Issue all 5 scattered DRAM loads first for max MLP, then the cached rows.
    float q[JMAX];
    #pragma unroll
    for (int j = 0; j < JMAX; j++) {
        const int v = j * 32 + lane;
        q[j] = (v < U) ? __ldg(qcol + (size_t)v * I) : 0.0f;
    }
    #pragma unroll
    for (int j = 0; j < JMAX; j++) {
        const int v = j * 32 + lane;
        const bool ok = v < U;
        float s = ok ? __ldg(simrow + v) : 0.0f;
        float a = ok ? __ldg(avgrow + v) : 0.0f;
        sv[j] = s;
        dv[j] = q[j] - a;
        // Reference semantics: sim_m = rated ? sim : 0.0 (zeros stay in the
        // candidate pool); only v>=U padding is removed entirely.
        float m = (q[j] > 0.0f) ? s : 0.0f;
        o[j] = ok ? f2ord(m) : 0u;
    }

    // Lane-local running best (value-ordered key, smallest j wins ties ->
    // code order == global user index order == jax top_k tie-break).
    unsigned lb = 0u; int lj = 0;
    #pragma unroll
    for (int j = 0; j < JMAX; j++) {
        if (o[j] > lb) { lb = o[j]; lj = j; }
    }

    float contrib = 0.0f;  // lane-local partial of sum_k w_k * d_k (unnormalized)
    float simsum  = 0.0f;  // uniform across lanes

    #pragma unroll
    for (int k = 0; k < 10; k++) {
        const unsigned m = __reduce_max_sync(0xffffffffu, lb);
        // Tie-break: minimum global user index among lanes holding m.
        const unsigned mycode = (unsigned)((lj << 5) | lane);
        const unsigned c  = (lb == m) ? mycode : 0xffffffffu;
        const unsigned wc = __reduce_min_sync(0xffffffffu, c);

        simsum += ord2f(m);

        if (wc == mycode && lb == m) {  // exactly one lane
            const float w = ord2f(m);
            #pragma unroll
            for (int j = 0; j < JMAX; j++) {
                if (j == lj) { contrib += w * dv[j]; o[j] = 0u; }
            }
            // Recompute this lane's local best (others unchanged).
            lb = 0u; lj = 0;
            #pragma unroll
            for (int j = 0; j < JMAX; j++) {
                if (o[j] > lb) { lb = o[j]; lj = j; }
            }
        }
    }

    // One cross-lane reduction of contrib at the end (replaces 10 broadcasts).
    #pragma unroll
    for (int off = 16; off; off >>= 1)
        contrib += __shfl_xor_sync(0xffffffffu, contrib, off);

    if (lane == 0) {
        const float s = simsum + 1e-8f;
        float p = contrib / s;
        if (!isfinite(p)) p = 0.0f;  // mirrors jnp.nan_to_num on degenerate sums
        out[warp] = avg_u + p;
    }
}

extern "C" void kernel_launch(void* const* d_in, const int* in_sizes, int n_in,
                              void* d_out, int out_size)
{
    const float* qos      = (const float*)d_in[0];
    const float* user_avg = (const float*)d_in[1];
    const float* sim      = (const float*)d_in[2];
    const int*   user_id  = (const int*)d_in[3];
    const int*   item_id  = (const int*)d_in[4];
    const int*   time_id  = (const int*)d_in[5];
    float* out = (float*)d_out;

    int U = (int)(sqrt((double)in_sizes[2]) + 0.5);
    int T = in_sizes[1] / U;
    int I = in_sizes[0] / (T * U);
    int B = in_sizes[3];

    const int threads = 256;  // 8 warps/block
    const int wpb = threads / 32;
    const int blocks = (B + wpb - 1) / wpb;
    ucf_kernel<<<blocks, threads>>>(qos, user_avg, sim,
                                    user_id, item_id, time_id,
                                    out, B, U, I);
}